// round 15
// baseline (speedup 1.0000x reference)
#include <cuda_runtime.h>
#include <math.h>

#define B 128
#define N 996
#define BN (B*N)
#define DIM 16
#define QKD 128
#define GSZ 256
#define NG 4
#define DEPTH 8
#define VOC 1024
#define ROTD 32

// ---------------- scratch ----------------
__device__ __align__(16) float g_x[BN*DIM];
__device__ __align__(16) float g_qo[BN*32];
__device__ __align__(16) float g_lq[BN*128];         // lin_q emitted by kA
__device__ __align__(16) float g_linkvp[B*8*128*32];
__device__ float g_rc[N*16];
__device__ float g_rs[N*16];
__device__ float g_hmax[BN];

#define ROT_LC 0.57564627324851142
#define POS_LC 1.1512925464970228

typedef unsigned long long ull;

__device__ __forceinline__ ull pk2(float a, float b) {
    ull r; asm("mov.b64 %0,{%1,%2};" : "=l"(r) : "f"(a), "f"(b)); return r;
}
__device__ __forceinline__ void fma2(ull& d, ull a, ull b) {
    asm("fma.rn.f32x2 %0,%1,%2,%0;" : "+l"(d) : "l"(a), "l"(b));
}
__device__ __forceinline__ float2 up2(ull v) {
    float2 f; asm("mov.b64 {%0,%1},%2;" : "=f"(f.x), "=f"(f.y) : "l"(v)); return f;
}
__device__ __forceinline__ float silu_f(float a) {
    return __fdividef(a, 1.0f + __expf(-a));
}
__device__ __forceinline__ unsigned f2tf(float f) {
    unsigned r; asm("cvt.rna.tf32.f32 %0,%1;" : "=r"(r) : "f"(f)); return r;
}
__device__ __forceinline__ void mma8(float* c, const unsigned* a, unsigned b0, unsigned b1) {
    asm volatile("mma.sync.aligned.m16n8k8.row.col.f32.tf32.tf32.f32 "
                 "{%0,%1,%2,%3},{%4,%5,%6,%7},{%8,%9},{%0,%1,%2,%3};"
                 : "+f"(c[0]), "+f"(c[1]), "+f"(c[2]), "+f"(c[3])
                 : "r"(a[0]), "r"(a[1]), "r"(a[2]), "r"(a[3]), "r"(b0), "r"(b1));
}

// proj 8 outputs [u0,u0+8)
__device__ __forceinline__ void proj8(const float* nmA, const float* nmB,
                                      const float* __restrict__ W, int ws,
                                      const float* __restrict__ bias, int u0, float* o) {
    #pragma unroll
    for (int j = 0; j < 8; j++) o[j] = bias[u0 + j];
    #pragma unroll
    for (int d = 0; d < 8; d++) { float a = nmA[d];
        #pragma unroll
        for (int j = 0; j < 8; j++) o[j] += a * W[d * ws + u0 + j]; }
    #pragma unroll
    for (int d = 0; d < 8; d++) { float a = nmB[d];
        #pragma unroll
        for (int j = 0; j < 8; j++) o[j] += a * W[(d + 8) * ws + u0 + j]; }
}
__device__ __forceinline__ void gbrot8(float* o, int u0, const float* __restrict__ gb, int pos) {
    #pragma unroll
    for (int jj = 0; jj < 8; jj++) o[jj] = silu_f(o[jj]);
    if (u0 < ROTD) {
        #pragma unroll
        for (int jj = 0; jj < 8; jj += 2) {
            int u = u0 + jj;
            float a = o[jj] * gb[u] + gb[128 + u];
            float b = o[jj+1] * gb[u+1] + gb[128 + u + 1];
            float c = g_rc[pos * 16 + (u >> 1)], s = g_rs[pos * 16 + (u >> 1)];
            o[jj] = a * c - b * s;
            o[jj+1] = b * c + a * s;
        }
    } else {
        #pragma unroll
        for (int jj = 0; jj < 8; jj++) { int u = u0 + jj; o[jj] = o[jj] * gb[u] + gb[128 + u]; }
    }
}
// same but input already silu'd
__device__ __forceinline__ void gb8(float* o, int u0, const float* __restrict__ gb, int pos) {
    if (u0 < ROTD) {
        #pragma unroll
        for (int jj = 0; jj < 8; jj += 2) {
            int u = u0 + jj;
            float a = o[jj] * gb[u] + gb[128 + u];
            float b = o[jj+1] * gb[u+1] + gb[128 + u + 1];
            float c = g_rc[pos * 16 + (u >> 1)], s = g_rs[pos * 16 + (u >> 1)];
            o[jj] = a * c - b * s;
            o[jj+1] = b * c + a * s;
        }
    } else {
        #pragma unroll
        for (int jj = 0; jj < 8; jj++) { int u = u0 + jj; o[jj] = o[jj] * gb[u] + gb[128 + u]; }
    }
}

// ---------------- K0 / K0b ----------------
__global__ void k_embed(const int* __restrict__ kmer, const float* __restrict__ emb,
                        const float* __restrict__ ps) {
    int idx = blockIdx.x * blockDim.x + threadIdx.x;
    if (idx >= BN * DIM) return;
    int d = idx & 15;
    int tok = idx >> 4;
    int t = tok % N;
    int j = (d < 8) ? d : d - 8;
    float inv = (float)exp(-(double)j * POS_LC);
    float ang = (float)t * inv;
    float p = (d < 8) ? sinf(ang) : cosf(ang);
    g_x[idx] = emb[kmer[tok] * DIM + d] + p * ps[0];
}
__global__ void k_rot() {
    int idx = blockIdx.x * blockDim.x + threadIdx.x;
    if (idx >= N * 16) return;
    int t = idx >> 4, j = idx & 15;
    float inv = (float)exp(-(double)j * ROT_LC);
    float ang = (float)t * inv;
    g_rc[idx] = cosf(ang);
    g_rs[idx] = sinf(ang);
}

// ---------------- kA: fused norm+proj + tf32-mma quad attention + lin_q emit + lin-KV partial ----------------
#define OF_SN  0
#define OF_QS  4372       // [128][132] fp32
#define OF_KTH 21268      // [128][72] tf32 hi
#define OF_KTL 30484
#define OF_VS  39700      // [64][40]
#define OF_WQK 42260
#define OF_WV  44308
#define OF_GBQ 44820
#define OF_GBK 45076
#define OF_BQK 45332
#define OF_BV  45460
#define OF_GB3 45492
#define OF_GB1 45748      // gamma|beta lin_q (row 1)
#define OF_LK  46004      // [64][136]
#define KA_SMEM ((46004 + 8704 + 12) * 4)   // 218880 B

__global__ void __launch_bounds__(256, 1) kA(const float* __restrict__ ng,
        const float* __restrict__ Wh, const float* __restrict__ bh,
        const float* __restrict__ Wqk, const float* __restrict__ bqk,
        const float* __restrict__ gamma, const float* __restrict__ beta) {
    extern __shared__ float s[];
    float* SN = s + OF_SN;  float* QS = s + OF_QS;
    unsigned* KTH = (unsigned*)(s + OF_KTH);
    unsigned* KTL = (unsigned*)(s + OF_KTL);
    float* VS = s + OF_VS;  float* WQ = s + OF_WQK;
    float* WV = s + OF_WV;  float* GQ = s + OF_GBQ; float* GK = s + OF_GBK;
    float* BQ = s + OF_BQK; float* BV = s + OF_BV;  float* G3 = s + OF_GB3;
    float* G1 = s + OF_GB1; float* LK = s + OF_LK;
    int tid = threadIdx.x;
    int lane = tid & 31, wid = tid >> 5;
    int r8 = lane >> 2, t4 = lane & 3;
    int qh = blockIdx.x, g = blockIdx.y, b = blockIdx.z;
    int gstart = g * GSZ;
    const int bN = b * N;

    for (int i = tid; i < 2048; i += 256) WQ[i] = Wqk[i];
    for (int i = tid; i < 512; i += 256) WV[i] = Wh[(i >> 5) * 64 + (i & 31)];
    if (tid < 128) {
        GQ[tid] = gamma[tid];       GQ[128 + tid] = beta[tid];
        GK[tid] = gamma[256 + tid]; GK[128 + tid] = beta[256 + tid];
        G3[tid] = gamma[384 + tid]; G3[128 + tid] = beta[384 + tid];
        G1[tid] = gamma[128 + tid]; G1[128 + tid] = beta[128 + tid];
        BQ[tid] = bqk[tid];
    }
    if (tid < 32) BV[tid] = bh[tid];
    for (int i = tid; i < 257 * 4; i += 256) {
        int r = i >> 2, d4 = (i & 3) * 4;
        int p = gstart - 1 + r;
        float4 v = make_float4(0, 0, 0, 0);
        if (p >= 0 && p < N) v = *(const float4*)&g_x[(long)(bN + p) * 16 + d4];
        SN[r*17 + d4] = v.x; SN[r*17 + d4+1] = v.y; SN[r*17 + d4+2] = v.z; SN[r*17 + d4+3] = v.w;
    }
    __syncthreads();
    float gng = ng[0];
    for (int i = tid; i < 257; i += 256) {
        float ss = 0;
        #pragma unroll
        for (int d = 0; d < 16; d++) { float v = SN[i*17 + d]; ss += v * v; }
        float scl = gng / fmaxf(sqrtf(ss) * 0.25f, 1e-5f);
        #pragma unroll
        for (int d = 0; d < 16; d++) SN[i*17 + d] *= scl;
    }
    __syncthreads();

    {   // Q tile + lin_q emit
        int j = tid >> 1, h = tid & 1;
        int p = gstart + qh * 128 + j;
        int si = qh * 128 + j + 1;
        float nmA[8], nmB[8];
        bool first = (p == 0);
        #pragma unroll
        for (int d = 0; d < 8; d++) {
            nmA[d] = first ? 0.0f : SN[(si - 1) * 17 + d];
            nmB[d] = SN[si * 17 + 8 + d];
        }
        int rp = (p < N) ? p : 0;
        #pragma unroll
        for (int c = 0; c < 8; c++) {
            int u0 = h * 64 + c * 8;
            float o[8], o2[8];
            proj8(nmA, nmB, WQ, 128, BQ, u0, o);
            #pragma unroll
            for (int jj = 0; jj < 8; jj++) { o[jj] = silu_f(o[jj]); o2[jj] = o[jj]; }
            gb8(o, u0, GQ, rp);
            gb8(o2, u0, G1, rp);
            #pragma unroll
            for (int jj = 0; jj < 8; jj += 2)
                *(float2*)&QS[j * 132 + u0 + jj] = make_float2(o[jj], o[jj+1]);
            if (p < N) {
                #pragma unroll
                for (int jj = 0; jj < 8; jj += 4)
                    *(float4*)&g_lq[(long)(bN + p) * 128 + u0 + jj] =
                        make_float4(o2[jj], o2[jj+1], o2[jj+2], o2[jj+3]);
            }
        }
    }

    float co[4][4];
    #pragma unroll
    for (int a = 0; a < 4; a++)
        #pragma unroll
        for (int i = 0; i < 4; i++) co[a][i] = 0.0f;
    ull lkacc[8];
    #pragma unroll
    for (int e = 0; e < 8; e++) lkacc[e] = 0ull;
    int dd = tid & 127, e0v = (tid >> 7) * 16;
    int mrow = wid * 16 + r8;

    for (int ck = 0; ck < 4; ck++) {
        bool mylin = (qh == (ck >> 1));
        __syncthreads();
        {   int t = tid & 63, q4 = tid >> 6;
            int kloc = ck * 64 + t;
            int p = gstart + kloc;
            int si = kloc + 1;
            float nmA[8], nmB[8];
            bool first = (p == 0);
            #pragma unroll
            for (int d = 0; d < 8; d++) {
                nmA[d] = first ? 0.0f : SN[(si - 1) * 17 + d];
                nmB[d] = SN[si * 17 + 8 + d];
            }
            int rp = (p < N) ? p : 0;
            #pragma unroll
            for (int cc = 0; cc < 4; cc++) {
                int u0 = q4 * 32 + cc * 8;
                float o[8];
                proj8(nmA, nmB, WQ, 128, BQ, u0, o);
                gbrot8(o, u0, GK, rp);
                #pragma unroll
                for (int jj = 0; jj < 8; jj++) {
                    unsigned h2 = f2tf(o[jj]);
                    KTH[(u0 + jj) * 72 + t] = h2;
                    KTL[(u0 + jj) * 72 + t] = f2tf(o[jj] - __uint_as_float(h2));
                }
            }
            {   int e0 = q4 * 8;
                float o[8];
                proj8(nmA, nmB, WV, 32, BV, e0, o);
                #pragma unroll
                for (int jj = 0; jj < 8; jj++) VS[t * 40 + e0 + jj] = silu_f(o[jj]);
            }
            if (mylin) {
                #pragma unroll
                for (int cc = 0; cc < 4; cc++) {
                    int u0 = q4 * 32 + cc * 8;
                    float o[8];
                    proj8(nmA, nmB, WQ, 128, BQ, u0, o);
                    gbrot8(o, u0, G3, rp);
                    #pragma unroll
                    for (int jj = 0; jj < 8; jj++)
                        LK[t * 136 + u0 + jj] = (p < N) ? o[jj] : 0.0f;
                }
            }
        }
        __syncthreads();

        float cs[8][4];
        #pragma unroll
        for (int nt = 0; nt < 8; nt++)
            #pragma unroll
            for (int i = 0; i < 4; i++) cs[nt][i] = 0.0f;
        #pragma unroll 2
        for (int kt = 0; kt < 16; kt++) {
            int kc0 = kt * 8 + t4;
            float q0 = QS[mrow * 132 + kc0];
            float q1 = QS[(mrow + 8) * 132 + kc0];
            float q2 = QS[mrow * 132 + kc0 + 4];
            float q3 = QS[(mrow + 8) * 132 + kc0 + 4];
            unsigned ah[4], al[4];
            ah[0] = f2tf(q0); al[0] = f2tf(q0 - __uint_as_float(ah[0]));
            ah[1] = f2tf(q1); al[1] = f2tf(q1 - __uint_as_float(ah[1]));
            ah[2] = f2tf(q2); al[2] = f2tf(q2 - __uint_as_float(ah[2]));
            ah[3] = f2tf(q3); al[3] = f2tf(q3 - __uint_as_float(ah[3]));
            #pragma unroll
            for (int nt = 0; nt < 8; nt++) {
                unsigned bh0 = KTH[kc0 * 72 + nt * 8 + r8];
                unsigned bh1 = KTH[(kc0 + 4) * 72 + nt * 8 + r8];
                unsigned bl0 = KTL[kc0 * 72 + nt * 8 + r8];
                unsigned bl1 = KTL[(kc0 + 4) * 72 + nt * 8 + r8];
                mma8(cs[nt], ah, bh0, bh1);
                mma8(cs[nt], ah, bl0, bl1);
                mma8(cs[nt], al, bh0, bh1);
            }
        }
        {   int kb = gstart + ck * 64;
            #pragma unroll
            for (int nt = 0; nt < 8; nt++) {
                int col0 = kb + nt * 8 + 2 * t4;
                float e00 = fmaxf(cs[nt][0] * (1.0f/256.0f), 0.0f); e00 *= e00;
                float e01 = fmaxf(cs[nt][1] * (1.0f/256.0f), 0.0f); e01 *= e01;
                float e10 = fmaxf(cs[nt][2] * (1.0f/256.0f), 0.0f); e10 *= e10;
                float e11 = fmaxf(cs[nt][3] * (1.0f/256.0f), 0.0f); e11 *= e11;
                if (col0     >= N) { e00 = 0.0f; e10 = 0.0f; }
                if (col0 + 1 >= N) { e01 = 0.0f; e11 = 0.0f; }
                unsigned u00 = f2tf(e00), u01 = f2tf(e01);
                unsigned u10 = f2tf(e10), u11 = f2tf(e11);
                int srcA = (lane & ~3) | (t4 >> 1);
                int srcB = srcA + 2;
                unsigned w00A = __shfl_sync(0xffffffffu, u00, srcA);
                unsigned w01A = __shfl_sync(0xffffffffu, u01, srcA);
                unsigned w10A = __shfl_sync(0xffffffffu, u10, srcA);
                unsigned w11A = __shfl_sync(0xffffffffu, u11, srcA);
                unsigned w00B = __shfl_sync(0xffffffffu, u00, srcB);
                unsigned w01B = __shfl_sync(0xffffffffu, u01, srcB);
                unsigned w10B = __shfl_sync(0xffffffffu, u10, srcB);
                unsigned w11B = __shfl_sync(0xffffffffu, u11, srcB);
                bool odd = (t4 & 1);
                unsigned aF[4];
                aF[0] = odd ? w01A : w00A;
                aF[1] = odd ? w11A : w10A;
                aF[2] = odd ? w01B : w00B;
                aF[3] = odd ? w11B : w10B;
                #pragma unroll
                for (int av = 0; av < 4; av++) {
                    float v0 = VS[(nt * 8 + t4) * 40 + av * 8 + r8];
                    float v1 = VS[(nt * 8 + t4 + 4) * 40 + av * 8 + r8];
                    unsigned bh0 = f2tf(v0), bh1 = f2tf(v1);
                    unsigned bl0 = f2tf(v0 - __uint_as_float(bh0));
                    unsigned bl1 = f2tf(v1 - __uint_as_float(bh1));
                    mma8(co[av], aF, bh0, bh1);
                    mma8(co[av], aF, bl0, bl1);
                }
            }
        }
        if (mylin) {
            #pragma unroll 4
            for (int j = 0; j < 64; j++) {
                float lv = LK[j * 136 + dd];
                ull ld = pk2(lv, lv);
                const ull* vp = (const ull*)&VS[j * 40 + e0v];
                #pragma unroll
                for (int e = 0; e < 8; e++) fma2(lkacc[e], ld, vp[e]);
            }
        }
    }
    {   int qp0 = gstart + qh * 128 + mrow;
        #pragma unroll
        for (int av = 0; av < 4; av++) {
            if (qp0 < N)
                *(float2*)&g_qo[(long)(bN + qp0) * 32 + av * 8 + 2 * t4] =
                    make_float2(co[av][0], co[av][1]);
            if (qp0 + 8 < N)
                *(float2*)&g_qo[(long)(bN + qp0 + 8) * 32 + av * 8 + 2 * t4] =
                    make_float2(co[av][2], co[av][3]);
        }
    }
    {   float* dst = &g_linkvp[((long)(b * 8 + g * 2 + qh) * 128 + dd) * 32 + e0v];
        #pragma unroll
        for (int e = 0; e < 8; e++) { float2 f = up2(lkacc[e]); *(float2*)&dst[e * 2] = f; }
    }
}

// ---------------- kC: KV-reduce + lin_out (lq from gmem) + gate + Wo + residual ----------------
__global__ void __launch_bounds__(256, 2) kC(const float* __restrict__ ng,
        const float* __restrict__ Wh, const float* __restrict__ bh,
        const float* __restrict__ Wqk, const float* __restrict__ bqk,
        const float* __restrict__ gamma, const float* __restrict__ beta,
        const float* __restrict__ Wo, const float* __restrict__ bo) {
    __shared__ __align__(16) float SN[84 * 17];
    __shared__ __align__(16) float SKV[4096];
    __shared__ __align__(16) float WG[512];
    __shared__ __align__(16) float BG[32];
    __shared__ __align__(16) float SWO[512];
    __shared__ __align__(16) float SBO[16];
    __shared__ __align__(16) float SLQ[32 * 132];
    __shared__ __align__(16) float SG[32 * 33];
    __shared__ __align__(16) float OV[32 * 34];
    int tid = threadIdx.x;
    int ch = blockIdx.x, b = blockIdx.y;
    const int bN = b * N;
    int t0 = ch * 83;

    for (int i = tid; i < 512; i += 256) {
        WG[i] = Wh[(i >> 5) * 64 + 32 + (i & 31)];
        SWO[i] = Wo[i];
    }
    if (tid < 32) BG[tid] = bh[32 + tid];
    if (tid < 16) SBO[tid] = bo[tid];
    const float inv_n = 1.0f / (float)N;
    for (int i = tid; i < 1024; i += 256) {
        float4 ssum = make_float4(0, 0, 0, 0);
        #pragma unroll
        for (int k2 = 0; k2 < 8; k2++) {
            float4 p = ((const float4*)&g_linkvp[(long)(b * 8 + k2) * 4096])[i];
            ssum.x += p.x; ssum.y += p.y; ssum.z += p.z; ssum.w += p.w;
        }
        ((float4*)SKV)[i] = make_float4(ssum.x * inv_n, ssum.y * inv_n, ssum.z * inv_n, ssum.w * inv_n);
    }
    for (int i = tid; i < 84 * 4; i += 256) {
        int r = i >> 2, d4 = (i & 3) * 4;
        int p = t0 - 1 + r;
        float4 v = make_float4(0, 0, 0, 0);
        if (p >= 0 && p < N) v = *(const float4*)&g_x[(long)(bN + p) * 16 + d4];
        SN[r*17 + d4] = v.x; SN[r*17 + d4+1] = v.y; SN[r*17 + d4+2] = v.z; SN[r*17 + d4+3] = v.w;
    }
    __syncthreads();
    float gng = ng[0];
    for (int i = tid; i < 84; i += 256) {
        float ss = 0;
        #pragma unroll
        for (int d = 0; d < 16; d++) { float v = SN[i*17 + d]; ss += v * v; }
        float scl = gng / fmaxf(sqrtf(ss) * 0.25f, 1e-5f);
        #pragma unroll
        for (int d = 0; d < 16; d++) SN[i*17 + d] *= scl;
    }

    int w = tid >> 5, lane = tid & 31;
    for (int tb = 0; tb < 96; tb += 32) {
        __syncthreads();
        // ---- P1: copy lq from gmem + gate proj ----
        for (int i = tid; i < 1024; i += 256) {
            int ltl = i >> 5;
            int d4 = (i & 31) * 4;
            int ltc = min(tb + ltl, 82);
            *(float4*)&SLQ[ltl * 132 + d4] =
                *(const float4*)&g_lq[(long)(bN + t0 + ltc) * 128 + d4];
        }
        #pragma unroll
        for (int i = 0; i < 4; i++) {
            int ltl = w * 4 + i;
            int ltc = min(tb + ltl, 82);
            int si = ltc + 1;
            bool first = (t0 + ltc == 0);
            float nmA[8], nmB[8];
            #pragma unroll
            for (int d = 0; d < 8; d++) {
                nmA[d] = first ? 0.0f : SN[(si - 1) * 17 + d];
                nmB[d] = SN[si * 17 + 8 + d];
            }
            float o = BG[lane];
            #pragma unroll
            for (int d = 0; d < 8; d++) o += nmA[d] * WG[d * 32 + lane];
            #pragma unroll
            for (int d = 0; d < 8; d++) o += nmB[d] * WG[(d + 8) * 32 + lane];
            SG[ltl * 33 + lane] = silu_f(o);
        }
        __syncthreads();
        // ---- P2: lin_out tile ----
        {
            int tt = tid >> 3;
            int e4 = (tid & 7) * 4;
            ull a0 = 0ull, a1 = 0ull, b0 = 0ull, b1 = 0ull;
            #pragma unroll 8
            for (int d = 0; d < 128; d += 2) {
                float q0 = SLQ[tt * 132 + d];
                float q1 = SLQ[tt * 132 + d + 1];
                ulonglong2 kv0 = *(const ulonglong2*)&SKV[d * 32 + e4];
                ulonglong2 kv1 = *(const ulonglong2*)&SKV[(d + 1) * 32 + e4];
                ull qd0 = pk2(q0, q0), qd1 = pk2(q1, q1);
                fma2(a0, qd0, kv0.x); fma2(a1, qd0, kv0.y);
                fma2(b0, qd1, kv1.x); fma2(b1, qd1, kv1.y);
            }
            float2 fa0 = up2(a0), fa1 = up2(a1), fb0 = up2(b0), fb1 = up2(b1);
            int ltc = min(tb + tt, 82);
            int tok = t0 + ltc;
            float4 qo = *(const float4*)&g_qo[(long)(bN + tok) * 32 + e4];
            float g0 = SG[tt * 33 + e4],     g1 = SG[tt * 33 + e4 + 1];
            float g2 = SG[tt * 33 + e4 + 2], g3 = SG[tt * 33 + e4 + 3];
            OV[tt * 34 + e4]     = (qo.x + fa0.x + fb0.x) * g0;
            OV[tt * 34 + e4 + 1] = (qo.y + fa0.y + fb0.y) * g1;
            OV[tt * 34 + e4 + 2] = (qo.z + fa1.x + fb1.x) * g2;
            OV[tt * 34 + e4 + 3] = (qo.w + fa1.y + fb1.y) * g3;
        }
        __syncthreads();
        // ---- P3: Wo + residual ----
        {
            int dcol = tid & 15;
            int tt2 = tid >> 4;
            #pragma unroll
            for (int h = 0; h < 2; h++) {
                int ttw = tt2 + 16 * h;
                int lt = tb + ttw;
                if (lt < 83) {
                    float y = SBO[dcol];
                    #pragma unroll
                    for (int e = 0; e < 32; e++) y += OV[ttw * 34 + e] * SWO[e * 16 + dcol];
                    g_x[(long)(bN + t0 + lt) * 16 + dcol] += y;
                }
            }
        }
    }
}

// ---------------- k_logits / k_head ----------------
#define LOGITS_SMEM ((16*1024 + 1024 + 16*16) * 4)
__global__ void k_logits(const float* __restrict__ fg, const float* __restrict__ Wl,
                         const float* __restrict__ blv) {
    extern __shared__ float sm[];
    float* sW = sm;
    float* sb = sW + 16 * 1024;
    float* xn = sb + 1024;
    __shared__ float wred[8];
    __shared__ float xs[16];
    int tid = threadIdx.x;
    int base = blockIdx.x * 16;
    for (int i = tid; i < (16 * 1024) / 4; i += 256)
        ((float4*)sW)[i] = ((const float4*)Wl)[i];
    for (int i = tid; i < 1024; i += 256) sb[i] = blv[i];
    {   int tt = tid >> 4, d = tid & 15;
        xn[tt * 16 + d] = g_x[(long)(base + tt) * DIM + d];
    }
    __syncthreads();
    if (tid < 16) {
        float ss = 0;
        #pragma unroll
        for (int d = 0; d < 16; d++) { float v = xn[tid * 16 + d]; ss += v * v; }
        xs[tid] = fg[0] / fmaxf(sqrtf(ss) * 0.25f, 1e-5f);
    }
    __syncthreads();
    {   int tt = tid >> 4, d = tid & 15;
        xn[tt * 16 + d] *= xs[tt];
    }
    __syncthreads();
    int warp = tid >> 5, lane = tid & 31;
    int v0 = tid * 4;
    for (int tt = 0; tt < 16; tt++) {
        float s0 = sb[v0], s1 = sb[v0+1], s2 = sb[v0+2], s3 = sb[v0+3];
        #pragma unroll
        for (int d = 0; d < 16; d++) {
            float xv = xn[tt * 16 + d];
            float4 wv = *(const float4*)&sW[d * 1024 + v0];
            s0 += xv * wv.x; s1 += xv * wv.y; s2 += xv * wv.z; s3 += xv * wv.w;
        }
        float m = fmaxf(fmaxf(s0, s1), fmaxf(s2, s3));
        #pragma unroll
        for (int off = 16; off > 0; off >>= 1)
            m = fmaxf(m, __shfl_xor_sync(0xffffffff, m, off));
        if (lane == 0) wred[warp] = m;
        __syncthreads();
        if (tid == 0) {
            float mm = wred[0];
            #pragma unroll
            for (int j = 1; j < 8; j++) mm = fmaxf(mm, wred[j]);
            g_hmax[base + tt] = mm;
        }
        __syncthreads();
    }
}
__global__ void k_head(const float* __restrict__ W1, const float* __restrict__ b1,
                       const float* __restrict__ W2, const float* __restrict__ b2,
                       float* __restrict__ out) {
    __shared__ float red[8][32];
    __shared__ float rr[32];
    int tid = threadIdx.x;
    int b = blockIdx.x;
    int col = tid & 31, seg = tid >> 5;
    float acc = 0.0f;
    int t0 = seg * 125;
    int t1 = min(t0 + 125, N);
    for (int t = t0; t < t1; t++)
        acc += g_hmax[(long)b * N + t] * W1[t * 32 + col];
    red[seg][col] = acc;
    __syncthreads();
    if (tid < 32) {
        float ss = b1[tid];
        #pragma unroll
        for (int k = 0; k < 8; k++) ss += red[k][tid];
        rr[tid] = fmaxf(ss, 0.0f);
    }
    __syncthreads();
    if (tid == 0) {
        float o = b2[0];
        #pragma unroll
        for (int j = 0; j < 32; j++) o += rr[j] * W2[j];
        out[b] = o;
    }
}

// ---------------- launch ----------------
extern "C" void kernel_launch(void* const* d_in, const int* in_sizes, int n_in,
                              void* d_out, int out_size) {
    const int*   kmer    = (const int*)  d_in[0];
    const float* emb     = (const float*)d_in[1];
    const float* psc     = (const float*)d_in[2];
    const float* norm_g  = (const float*)d_in[3];
    const float* Wh      = (const float*)d_in[4];
    const float* bh      = (const float*)d_in[5];
    const float* Wqk     = (const float*)d_in[6];
    const float* bqk     = (const float*)d_in[7];
    const float* gamma   = (const float*)d_in[8];
    const float* beta    = (const float*)d_in[9];
    const float* Wo      = (const float*)d_in[10];
    const float* bo      = (const float*)d_in[11];
    const float* fg      = (const float*)d_in[12];
    const float* Wl      = (const float*)d_in[13];
    const float* bl      = (const float*)d_in[14];
    const float* W1      = (const float*)d_in[15];
    const float* b1      = (const float*)d_in[16];
    const float* W2      = (const float*)d_in[17];
    const float* b2      = (const float*)d_in[18];
    float* out = (float*)d_out;

    cudaFuncSetAttribute(kA, cudaFuncAttributeMaxDynamicSharedMemorySize, KA_SMEM);
    cudaFuncSetAttribute(k_logits, cudaFuncAttributeMaxDynamicSharedMemorySize, LOGITS_SMEM);

    k_embed<<<(BN * DIM + 255) / 256, 256>>>(kmer, emb, psc);
    k_rot<<<(N * 16 + 255) / 256, 256>>>();

    for (int l = 0; l < DEPTH; l++) {
        const float* Whl = Wh + (long)l * 16 * 64;
        const float* bhl = bh + (long)l * 64;
        const float* Wql = Wqk + (long)l * 16 * 128;
        const float* bql = bqk + (long)l * 128;
        const float* gml = gamma + (long)l * 4 * 128;
        const float* btl = beta + (long)l * 4 * 128;
        kA<<<dim3(2, NG, B), 256, KA_SMEM>>>(norm_g + l, Whl, bhl, Wql, bql, gml, btl);
        kC<<<dim3(12, B), 256>>>(norm_g + l, Whl, bhl, Wql, bql, gml, btl,
                                 Wo + (long)l * 32 * DIM, bo + (long)l * DIM);
    }

    k_logits<<<BN / 16, 256, LOGITS_SMEM>>>(fg, Wl, bl);
    k_head<<<B, 256>>>(W1, b1, W2, b2, out);
    (void)in_sizes; (void)n_in; (void)out_size;
}

// round 16
// speedup vs baseline: 1.0809x; 1.0809x over previous
#include <cuda_runtime.h>
#include <math.h>

#define B 128
#define N 996
#define BN (B*N)
#define DIM 16
#define QKD 128
#define GSZ 256
#define NG 4
#define DEPTH 8
#define VOC 1024
#define ROTD 32

// ---------------- scratch ----------------
__device__ __align__(16) float g_x[BN*DIM];
__device__ __align__(16) float g_qo[BN*32];
__device__ __align__(16) float g_linkvp[B*8*128*32];
__device__ float g_rc[N*16];
__device__ float g_rs[N*16];
__device__ float g_hmax[BN];

#define ROT_LC 0.57564627324851142
#define POS_LC 1.1512925464970228

typedef unsigned long long ull;

__device__ __forceinline__ ull pk2(float a, float b) {
    ull r; asm("mov.b64 %0,{%1,%2};" : "=l"(r) : "f"(a), "f"(b)); return r;
}
__device__ __forceinline__ void fma2(ull& d, ull a, ull b) {
    asm("fma.rn.f32x2 %0,%1,%2,%0;" : "+l"(d) : "l"(a), "l"(b));
}
__device__ __forceinline__ float2 up2(ull v) {
    float2 f; asm("mov.b64 {%0,%1},%2;" : "=f"(f.x), "=f"(f.y) : "l"(v)); return f;
}
__device__ __forceinline__ float silu_f(float a) {
    return __fdividef(a, 1.0f + __expf(-a));
}
__device__ __forceinline__ unsigned f2tf(float f) {
    unsigned r; asm("cvt.rna.tf32.f32 %0,%1;" : "=r"(r) : "f"(f)); return r;
}
__device__ __forceinline__ void mma8(float* c, const unsigned* a, unsigned b0, unsigned b1) {
    asm volatile("mma.sync.aligned.m16n8k8.row.col.f32.tf32.tf32.f32 "
                 "{%0,%1,%2,%3},{%4,%5,%6,%7},{%8,%9},{%0,%1,%2,%3};"
                 : "+f"(c[0]), "+f"(c[1]), "+f"(c[2]), "+f"(c[3])
                 : "r"(a[0]), "r"(a[1]), "r"(a[2]), "r"(a[3]), "r"(b0), "r"(b1));
}

// proj 8 outputs [u0,u0+8)
__device__ __forceinline__ void proj8(const float* nmA, const float* nmB,
                                      const float* __restrict__ W, int ws,
                                      const float* __restrict__ bias, int u0, float* o) {
    #pragma unroll
    for (int j = 0; j < 8; j++) o[j] = bias[u0 + j];
    #pragma unroll
    for (int d = 0; d < 8; d++) { float a = nmA[d];
        #pragma unroll
        for (int j = 0; j < 8; j++) o[j] += a * W[d * ws + u0 + j]; }
    #pragma unroll
    for (int d = 0; d < 8; d++) { float a = nmB[d];
        #pragma unroll
        for (int j = 0; j < 8; j++) o[j] += a * W[(d + 8) * ws + u0 + j]; }
}
// silu + gamma/beta + rotary
__device__ __forceinline__ void gbrot8(float* o, int u0, const float* __restrict__ gb, int pos) {
    #pragma unroll
    for (int jj = 0; jj < 8; jj++) o[jj] = silu_f(o[jj]);
    if (u0 < ROTD) {
        #pragma unroll
        for (int jj = 0; jj < 8; jj += 2) {
            int u = u0 + jj;
            float a = o[jj] * gb[u] + gb[128 + u];
            float b = o[jj+1] * gb[u+1] + gb[128 + u + 1];
            float c = g_rc[pos * 16 + (u >> 1)], s = g_rs[pos * 16 + (u >> 1)];
            o[jj] = a * c - b * s;
            o[jj+1] = b * c + a * s;
        }
    } else {
        #pragma unroll
        for (int jj = 0; jj < 8; jj++) { int u = u0 + jj; o[jj] = o[jj] * gb[u] + gb[128 + u]; }
    }
}
// gamma/beta + rotary only (input already silu'd)
__device__ __forceinline__ void gb8(float* o, int u0, const float* __restrict__ gb, int pos) {
    if (u0 < ROTD) {
        #pragma unroll
        for (int jj = 0; jj < 8; jj += 2) {
            int u = u0 + jj;
            float a = o[jj] * gb[u] + gb[128 + u];
            float b = o[jj+1] * gb[u+1] + gb[128 + u + 1];
            float c = g_rc[pos * 16 + (u >> 1)], s = g_rs[pos * 16 + (u >> 1)];
            o[jj] = a * c - b * s;
            o[jj+1] = b * c + a * s;
        }
    } else {
        #pragma unroll
        for (int jj = 0; jj < 8; jj++) { int u = u0 + jj; o[jj] = o[jj] * gb[u] + gb[128 + u]; }
    }
}

// ---------------- K0 / K0b ----------------
__global__ void k_embed(const int* __restrict__ kmer, const float* __restrict__ emb,
                        const float* __restrict__ ps) {
    int idx = blockIdx.x * blockDim.x + threadIdx.x;
    if (idx >= BN * DIM) return;
    int d = idx & 15;
    int tok = idx >> 4;
    int t = tok % N;
    int j = (d < 8) ? d : d - 8;
    float inv = (float)exp(-(double)j * POS_LC);
    float ang = (float)t * inv;
    float p = (d < 8) ? sinf(ang) : cosf(ang);
    g_x[idx] = emb[kmer[tok] * DIM + d] + p * ps[0];
}
__global__ void k_rot() {
    int idx = blockIdx.x * blockDim.x + threadIdx.x;
    if (idx >= N * 16) return;
    int t = idx >> 4, j = idx & 15;
    float inv = (float)exp(-(double)j * ROT_LC);
    float ang = (float)t * inv;
    g_rc[idx] = cosf(ang);
    g_rs[idx] = sinf(ang);
}

// ---------------- kA: fused norm+proj + tf32-mma quad attention + lin-KV partial ----------------
#define OF_SN  0
#define OF_QS  4372       // [128][132] fp32
#define OF_KTH 21268      // [128][72] tf32 hi
#define OF_KTL 30484
#define OF_VS  39700      // [64][40]
#define OF_WQK 42260
#define OF_WV  44308
#define OF_GBQ 44820
#define OF_GBK 45076
#define OF_BQK 45332
#define OF_BV  45460
#define OF_GB3 45492
#define OF_LK  45748      // [64][136]
#define KA_SMEM ((45748 + 8704 + 12) * 4)   // 217856 B

__global__ void __launch_bounds__(256, 1) kA(const float* __restrict__ ng,
        const float* __restrict__ Wh, const float* __restrict__ bh,
        const float* __restrict__ Wqk, const float* __restrict__ bqk,
        const float* __restrict__ gamma, const float* __restrict__ beta) {
    extern __shared__ float s[];
    float* SN = s + OF_SN;  float* QS = s + OF_QS;
    unsigned* KTH = (unsigned*)(s + OF_KTH);
    unsigned* KTL = (unsigned*)(s + OF_KTL);
    float* VS = s + OF_VS;  float* WQ = s + OF_WQK;
    float* WV = s + OF_WV;  float* GQ = s + OF_GBQ; float* GK = s + OF_GBK;
    float* BQ = s + OF_BQK; float* BV = s + OF_BV;  float* G3 = s + OF_GB3;
    float* LK = s + OF_LK;
    int tid = threadIdx.x;
    int lane = tid & 31, wid = tid >> 5;
    int r8 = lane >> 2, t4 = lane & 3;
    int qh = blockIdx.x, g = blockIdx.y, b = blockIdx.z;
    int gstart = g * GSZ;
    const int bN = b * N;

    for (int i = tid; i < 2048; i += 256) WQ[i] = Wqk[i];
    for (int i = tid; i < 512; i += 256) WV[i] = Wh[(i >> 5) * 64 + (i & 31)];
    if (tid < 128) {
        GQ[tid] = gamma[tid];       GQ[128 + tid] = beta[tid];
        GK[tid] = gamma[256 + tid]; GK[128 + tid] = beta[256 + tid];
        G3[tid] = gamma[384 + tid]; G3[128 + tid] = beta[384 + tid];
        BQ[tid] = bqk[tid];
    }
    if (tid < 32) BV[tid] = bh[tid];
    for (int i = tid; i < 257 * 4; i += 256) {
        int r = i >> 2, d4 = (i & 3) * 4;
        int p = gstart - 1 + r;
        float4 v = make_float4(0, 0, 0, 0);
        if (p >= 0 && p < N) v = *(const float4*)&g_x[(long)(bN + p) * 16 + d4];
        SN[r*17 + d4] = v.x; SN[r*17 + d4+1] = v.y; SN[r*17 + d4+2] = v.z; SN[r*17 + d4+3] = v.w;
    }
    __syncthreads();
    float gng = ng[0];
    for (int i = tid; i < 257; i += 256) {
        float ss = 0;
        #pragma unroll
        for (int d = 0; d < 16; d++) { float v = SN[i*17 + d]; ss += v * v; }
        float scl = gng / fmaxf(sqrtf(ss) * 0.25f, 1e-5f);
        #pragma unroll
        for (int d = 0; d < 16; d++) SN[i*17 + d] *= scl;
    }
    __syncthreads();

    {   // Q tile (128 q tokens x 128 dims) fp32
        int j = tid >> 1, h = tid & 1;
        int p = gstart + qh * 128 + j;
        int si = qh * 128 + j + 1;
        float nmA[8], nmB[8];
        bool first = (p == 0);
        #pragma unroll
        for (int d = 0; d < 8; d++) {
            nmA[d] = first ? 0.0f : SN[(si - 1) * 17 + d];
            nmB[d] = SN[si * 17 + 8 + d];
        }
        int rp = (p < N) ? p : 0;
        #pragma unroll
        for (int c = 0; c < 8; c++) {
            int u0 = h * 64 + c * 8;
            float o[8];
            proj8(nmA, nmB, WQ, 128, BQ, u0, o);
            gbrot8(o, u0, GQ, rp);
            #pragma unroll
            for (int jj = 0; jj < 8; jj += 2)
                *(float2*)&QS[j * 132 + u0 + jj] = make_float2(o[jj], o[jj+1]);
        }
    }

    float co[4][4];
    #pragma unroll
    for (int a = 0; a < 4; a++)
        #pragma unroll
        for (int i = 0; i < 4; i++) co[a][i] = 0.0f;
    ull lkacc[8];
    #pragma unroll
    for (int e = 0; e < 8; e++) lkacc[e] = 0ull;
    int dd = tid & 127, e0v = (tid >> 7) * 16;
    int mrow = wid * 16 + r8;

    for (int ck = 0; ck < 4; ck++) {
        bool mylin = (qh == (ck >> 1));
        __syncthreads();
        {   // build K chunk tf32 hi/lo + V chunk + (owned) lin_k via shared proj
            int t = tid & 63, q4 = tid >> 6;
            int kloc = ck * 64 + t;
            int p = gstart + kloc;
            int si = kloc + 1;
            float nmA[8], nmB[8];
            bool first = (p == 0);
            #pragma unroll
            for (int d = 0; d < 8; d++) {
                nmA[d] = first ? 0.0f : SN[(si - 1) * 17 + d];
                nmB[d] = SN[si * 17 + 8 + d];
            }
            int rp = (p < N) ? p : 0;
            #pragma unroll
            for (int cc = 0; cc < 4; cc++) {
                int u0 = q4 * 32 + cc * 8;
                float o[8];
                proj8(nmA, nmB, WQ, 128, BQ, u0, o);
                #pragma unroll
                for (int jj = 0; jj < 8; jj++) o[jj] = silu_f(o[jj]);
                if (mylin) {
                    float o2[8];
                    #pragma unroll
                    for (int jj = 0; jj < 8; jj++) o2[jj] = o[jj];
                    gb8(o2, u0, G3, rp);
                    #pragma unroll
                    for (int jj = 0; jj < 8; jj++)
                        LK[t * 136 + u0 + jj] = (p < N) ? o2[jj] : 0.0f;
                }
                gb8(o, u0, GK, rp);
                #pragma unroll
                for (int jj = 0; jj < 8; jj++) {
                    unsigned h2 = f2tf(o[jj]);
                    KTH[(u0 + jj) * 72 + t] = h2;
                    KTL[(u0 + jj) * 72 + t] = f2tf(o[jj] - __uint_as_float(h2));
                }
            }
            {   int e0 = q4 * 8;
                float o[8];
                proj8(nmA, nmB, WV, 32, BV, e0, o);
                #pragma unroll
                for (int jj = 0; jj < 8; jj++) VS[t * 40 + e0 + jj] = silu_f(o[jj]);
            }
        }
        __syncthreads();

        // ---- sim via tf32 mma ----
        float cs[8][4];
        #pragma unroll
        for (int nt = 0; nt < 8; nt++)
            #pragma unroll
            for (int i = 0; i < 4; i++) cs[nt][i] = 0.0f;
        #pragma unroll 2
        for (int kt = 0; kt < 16; kt++) {
            int kc0 = kt * 8 + t4;
            float q0 = QS[mrow * 132 + kc0];
            float q1 = QS[(mrow + 8) * 132 + kc0];
            float q2 = QS[mrow * 132 + kc0 + 4];
            float q3 = QS[(mrow + 8) * 132 + kc0 + 4];
            unsigned ah[4], al[4];
            ah[0] = f2tf(q0); al[0] = f2tf(q0 - __uint_as_float(ah[0]));
            ah[1] = f2tf(q1); al[1] = f2tf(q1 - __uint_as_float(ah[1]));
            ah[2] = f2tf(q2); al[2] = f2tf(q2 - __uint_as_float(ah[2]));
            ah[3] = f2tf(q3); al[3] = f2tf(q3 - __uint_as_float(ah[3]));
            #pragma unroll
            for (int nt = 0; nt < 8; nt++) {
                unsigned bh0 = KTH[kc0 * 72 + nt * 8 + r8];
                unsigned bh1 = KTH[(kc0 + 4) * 72 + nt * 8 + r8];
                unsigned bl0 = KTL[kc0 * 72 + nt * 8 + r8];
                unsigned bl1 = KTL[(kc0 + 4) * 72 + nt * 8 + r8];
                mma8(cs[nt], ah, bh0, bh1);
                mma8(cs[nt], ah, bl0, bl1);
                mma8(cs[nt], al, bh0, bh1);
            }
        }
        // ---- epilogue + A@V mma ----
        {   int kb = gstart + ck * 64;
            #pragma unroll
            for (int nt = 0; nt < 8; nt++) {
                int col0 = kb + nt * 8 + 2 * t4;
                float e00 = fmaxf(cs[nt][0] * (1.0f/256.0f), 0.0f); e00 *= e00;
                float e01 = fmaxf(cs[nt][1] * (1.0f/256.0f), 0.0f); e01 *= e01;
                float e10 = fmaxf(cs[nt][2] * (1.0f/256.0f), 0.0f); e10 *= e10;
                float e11 = fmaxf(cs[nt][3] * (1.0f/256.0f), 0.0f); e11 *= e11;
                if (col0     >= N) { e00 = 0.0f; e10 = 0.0f; }
                if (col0 + 1 >= N) { e01 = 0.0f; e11 = 0.0f; }
                unsigned u00 = f2tf(e00), u01 = f2tf(e01);
                unsigned u10 = f2tf(e10), u11 = f2tf(e11);
                int srcA = (lane & ~3) | (t4 >> 1);
                int srcB = srcA + 2;
                unsigned w00A = __shfl_sync(0xffffffffu, u00, srcA);
                unsigned w01A = __shfl_sync(0xffffffffu, u01, srcA);
                unsigned w10A = __shfl_sync(0xffffffffu, u10, srcA);
                unsigned w11A = __shfl_sync(0xffffffffu, u11, srcA);
                unsigned w00B = __shfl_sync(0xffffffffu, u00, srcB);
                unsigned w01B = __shfl_sync(0xffffffffu, u01, srcB);
                unsigned w10B = __shfl_sync(0xffffffffu, u10, srcB);
                unsigned w11B = __shfl_sync(0xffffffffu, u11, srcB);
                bool odd = (t4 & 1);
                unsigned aF[4];
                aF[0] = odd ? w01A : w00A;
                aF[1] = odd ? w11A : w10A;
                aF[2] = odd ? w01B : w00B;
                aF[3] = odd ? w11B : w10B;
                #pragma unroll
                for (int av = 0; av < 4; av++) {
                    float v0 = VS[(nt * 8 + t4) * 40 + av * 8 + r8];
                    float v1 = VS[(nt * 8 + t4 + 4) * 40 + av * 8 + r8];
                    unsigned bh0 = f2tf(v0), bh1 = f2tf(v1);
                    unsigned bl0 = f2tf(v0 - __uint_as_float(bh0));
                    unsigned bl1 = f2tf(v1 - __uint_as_float(bh1));
                    mma8(co[av], aF, bh0, bh1);
                    mma8(co[av], aF, bl0, bl1);
                }
            }
        }
        if (mylin) {
            #pragma unroll 4
            for (int j = 0; j < 64; j++) {
                float lv = LK[j * 136 + dd];
                ull ld = pk2(lv, lv);
                const ull* vp = (const ull*)&VS[j * 40 + e0v];
                #pragma unroll
                for (int e = 0; e < 8; e++) fma2(lkacc[e], ld, vp[e]);
            }
        }
    }
    {   int qp0 = gstart + qh * 128 + mrow;
        #pragma unroll
        for (int av = 0; av < 4; av++) {
            if (qp0 < N)
                *(float2*)&g_qo[(long)(bN + qp0) * 32 + av * 8 + 2 * t4] =
                    make_float2(co[av][0], co[av][1]);
            if (qp0 + 8 < N)
                *(float2*)&g_qo[(long)(bN + qp0 + 8) * 32 + av * 8 + 2 * t4] =
                    make_float2(co[av][2], co[av][3]);
        }
    }
    {   float* dst = &g_linkvp[((long)(b * 8 + g * 2 + qh) * 128 + dd) * 32 + e0v];
        #pragma unroll
        for (int e = 0; e < 8; e++) { float2 f = up2(lkacc[e]); *(float2*)&dst[e * 2] = f; }
    }
}

// ---------------- kC: KV-reduce + lin_out (tiled) + gate + Wo + residual ----------------
__global__ void __launch_bounds__(256, 2) kC(const float* __restrict__ ng,
        const float* __restrict__ Wh, const float* __restrict__ bh,
        const float* __restrict__ Wqk, const float* __restrict__ bqk,
        const float* __restrict__ gamma, const float* __restrict__ beta,
        const float* __restrict__ Wo, const float* __restrict__ bo) {
    __shared__ __align__(16) float SN[84 * 17];
    __shared__ __align__(16) float SKV[4096];
    __shared__ __align__(16) float WQ[2048];
    __shared__ __align__(16) float WG[512];
    __shared__ __align__(16) float GB[256];
    __shared__ __align__(16) float BQ2[128];
    __shared__ __align__(16) float BG[32];
    __shared__ __align__(16) float SWO[512];
    __shared__ __align__(16) float SBO[16];
    __shared__ __align__(16) float SLQ[32 * 132];
    __shared__ __align__(16) float SG[32 * 33];
    __shared__ __align__(16) float OV[32 * 34];
    int tid = threadIdx.x;
    int ch = blockIdx.x, b = blockIdx.y;
    const int bN = b * N;
    int t0 = ch * 83;

    for (int i = tid; i < 2048; i += 256) WQ[i] = Wqk[i];
    for (int i = tid; i < 512; i += 256) {
        WG[i] = Wh[(i >> 5) * 64 + 32 + (i & 31)];
        SWO[i] = Wo[i];
    }
    if (tid < 128) {
        GB[tid] = gamma[128 + tid]; GB[128 + tid] = beta[128 + tid];
        BQ2[tid] = bqk[tid];
    }
    if (tid < 32) BG[tid] = bh[32 + tid];
    if (tid < 16) SBO[tid] = bo[tid];
    const float inv_n = 1.0f / (float)N;
    for (int i = tid; i < 1024; i += 256) {
        float4 ssum = make_float4(0, 0, 0, 0);
        #pragma unroll
        for (int k2 = 0; k2 < 8; k2++) {
            float4 p = ((const float4*)&g_linkvp[(long)(b * 8 + k2) * 4096])[i];
            ssum.x += p.x; ssum.y += p.y; ssum.z += p.z; ssum.w += p.w;
        }
        ((float4*)SKV)[i] = make_float4(ssum.x * inv_n, ssum.y * inv_n, ssum.z * inv_n, ssum.w * inv_n);
    }
    for (int i = tid; i < 84 * 4; i += 256) {
        int r = i >> 2, d4 = (i & 3) * 4;
        int p = t0 - 1 + r;
        float4 v = make_float4(0, 0, 0, 0);
        if (p >= 0 && p < N) v = *(const float4*)&g_x[(long)(bN + p) * 16 + d4];
        SN[r*17 + d4] = v.x; SN[r*17 + d4+1] = v.y; SN[r*17 + d4+2] = v.z; SN[r*17 + d4+3] = v.w;
    }
    __syncthreads();
    float gng = ng[0];
    for (int i = tid; i < 84; i += 256) {
        float ss = 0;
        #pragma unroll
        for (int d = 0; d < 16; d++) { float v = SN[i*17 + d]; ss += v * v; }
        float scl = gng / fmaxf(sqrtf(ss) * 0.25f, 1e-5f);
        #pragma unroll
        for (int d = 0; d < 16; d++) SN[i*17 + d] *= scl;
    }

    int w = tid >> 5, lane = tid & 31;
    for (int tb = 0; tb < 96; tb += 32) {
        __syncthreads();
        #pragma unroll
        for (int i = 0; i < 4; i++) {
            int ltl = w * 4 + i;
            int lt = tb + ltl;
            int ltc = min(lt, 82);
            int tok = t0 + ltc;
            int si = ltc + 1;
            bool first = (tok == 0);
            float nmA[8], nmB[8];
            #pragma unroll
            for (int d = 0; d < 8; d++) {
                nmA[d] = first ? 0.0f : SN[(si - 1) * 17 + d];
                nmB[d] = SN[si * 17 + 8 + d];
            }
            #pragma unroll
            for (int j = 0; j < 4; j++) {
                int u = lane + 32 * j;
                float o = BQ2[u];
                #pragma unroll
                for (int d = 0; d < 8; d++) o += nmA[d] * WQ[d * 128 + u];
                #pragma unroll
                for (int d = 0; d < 8; d++) o += nmB[d] * WQ[(d + 8) * 128 + u];
                o = silu_f(o);
                o = o * GB[u] + GB[128 + u];
                if (j == 0) {
                    float c = g_rc[tok * 16 + (lane >> 1)], sn2 = g_rs[tok * 16 + (lane >> 1)];
                    float part = __shfl_xor_sync(0xffffffffu, o, 1);
                    o = (lane & 1) ? (o * c + part * sn2) : (o * c - part * sn2);
                }
                SLQ[ltl * 132 + u] = o;
            }
            {   float o = BG[lane];
                #pragma unroll
                for (int d = 0; d < 8; d++) o += nmA[d] * WG[d * 32 + lane];
                #pragma unroll
                for (int d = 0; d < 8; d++) o += nmB[d] * WG[(d + 8) * 32 + lane];
                SG[ltl * 33 + lane] = silu_f(o);
            }
        }
        __syncthreads();
        {
            int tt = tid >> 3;
            int e4 = (tid & 7) * 4;
            ull a0 = 0ull, a1 = 0ull, b0 = 0ull, b1 = 0ull;
            #pragma unroll 8
            for (int d = 0; d < 128; d += 2) {
                float q0 = SLQ[tt * 132 + d];
                float q1 = SLQ[tt * 132 + d + 1];
                ulonglong2 kv0 = *(const ulonglong2*)&SKV[d * 32 + e4];
                ulonglong2 kv1 = *(const ulonglong2*)&SKV[(d + 1) * 32 + e4];
                ull qd0 = pk2(q0, q0), qd1 = pk2(q1, q1);
                fma2(a0, qd0, kv0.x); fma2(a1, qd0, kv0.y);
                fma2(b0, qd1, kv1.x); fma2(b1, qd1, kv1.y);
            }
            float2 fa0 = up2(a0), fa1 = up2(a1), fb0 = up2(b0), fb1 = up2(b1);
            int lt = tb + tt;
            int ltc = min(lt, 82);
            int tok = t0 + ltc;
            float4 qo = *(const float4*)&g_qo[(long)(bN + tok) * 32 + e4];
            float g0 = SG[tt * 33 + e4],     g1 = SG[tt * 33 + e4 + 1];
            float g2 = SG[tt * 33 + e4 + 2], g3 = SG[tt * 33 + e4 + 3];
            OV[tt * 34 + e4]     = (qo.x + fa0.x + fb0.x) * g0;
            OV[tt * 34 + e4 + 1] = (qo.y + fa0.y + fb0.y) * g1;
            OV[tt * 34 + e4 + 2] = (qo.z + fa1.x + fb1.x) * g2;
            OV[tt * 34 + e4 + 3] = (qo.w + fa1.y + fb1.y) * g3;
        }
        __syncthreads();
        {
            int dcol = tid & 15;
            int tt2 = tid >> 4;
            #pragma unroll
            for (int h = 0; h < 2; h++) {
                int ttw = tt2 + 16 * h;
                int lt = tb + ttw;
                if (lt < 83) {
                    float y = SBO[dcol];
                    #pragma unroll
                    for (int e = 0; e < 32; e++) y += OV[ttw * 34 + e] * SWO[e * 16 + dcol];
                    g_x[(long)(bN + t0 + lt) * 16 + dcol] += y;
                }
            }
        }
    }
}

// ---------------- k_logits / k_head ----------------
#define LOGITS_SMEM ((16*1024 + 1024 + 16*16) * 4)
__global__ void k_logits(const float* __restrict__ fg, const float* __restrict__ Wl,
                         const float* __restrict__ blv) {
    extern __shared__ float sm[];
    float* sW = sm;
    float* sb = sW + 16 * 1024;
    float* xn = sb + 1024;
    __shared__ float wred[8];
    __shared__ float xs[16];
    int tid = threadIdx.x;
    int base = blockIdx.x * 16;
    for (int i = tid; i < (16 * 1024) / 4; i += 256)
        ((float4*)sW)[i] = ((const float4*)Wl)[i];
    for (int i = tid; i < 1024; i += 256) sb[i] = blv[i];
    {   int tt = tid >> 4, d = tid & 15;
        xn[tt * 16 + d] = g_x[(long)(base + tt) * DIM + d];
    }
    __syncthreads();
    if (tid < 16) {
        float ss = 0;
        #pragma unroll
        for (int d = 0; d < 16; d++) { float v = xn[tid * 16 + d]; ss += v * v; }
        xs[tid] = fg[0] / fmaxf(sqrtf(ss) * 0.25f, 1e-5f);
    }
    __syncthreads();
    {   int tt = tid >> 4, d = tid & 15;
        xn[tt * 16 + d] *= xs[tt];
    }
    __syncthreads();
    int warp = tid >> 5, lane = tid & 31;
    int v0 = tid * 4;
    for (int tt = 0; tt < 16; tt++) {
        float s0 = sb[v0], s1 = sb[v0+1], s2 = sb[v0+2], s3 = sb[v0+3];
        #pragma unroll
        for (int d = 0; d < 16; d++) {
            float xv = xn[tt * 16 + d];
            float4 wv = *(const float4*)&sW[d * 1024 + v0];
            s0 += xv * wv.x; s1 += xv * wv.y; s2 += xv * wv.z; s3 += xv * wv.w;
        }
        float m = fmaxf(fmaxf(s0, s1), fmaxf(s2, s3));
        #pragma unroll
        for (int off = 16; off > 0; off >>= 1)
            m = fmaxf(m, __shfl_xor_sync(0xffffffff, m, off));
        if (lane == 0) wred[warp] = m;
        __syncthreads();
        if (tid == 0) {
            float mm = wred[0];
            #pragma unroll
            for (int j = 1; j < 8; j++) mm = fmaxf(mm, wred[j]);
            g_hmax[base + tt] = mm;
        }
        __syncthreads();
    }
}
__global__ void k_head(const float* __restrict__ W1, const float* __restrict__ b1,
                       const float* __restrict__ W2, const float* __restrict__ b2,
                       float* __restrict__ out) {
    __shared__ float red[8][32];
    __shared__ float rr[32];
    int tid = threadIdx.x;
    int b = blockIdx.x;
    int col = tid & 31, seg = tid >> 5;
    float acc = 0.0f;
    int t0 = seg * 125;
    int t1 = min(t0 + 125, N);
    for (int t = t0; t < t1; t++)
        acc += g_hmax[(long)b * N + t] * W1[t * 32 + col];
    red[seg][col] = acc;
    __syncthreads();
    if (tid < 32) {
        float ss = b1[tid];
        #pragma unroll
        for (int k = 0; k < 8; k++) ss += red[k][tid];
        rr[tid] = fmaxf(ss, 0.0f);
    }
    __syncthreads();
    if (tid == 0) {
        float o = b2[0];
        #pragma unroll
        for (int j = 0; j < 32; j++) o += rr[j] * W2[j];
        out[b] = o;
    }
}

// ---------------- launch ----------------
extern "C" void kernel_launch(void* const* d_in, const int* in_sizes, int n_in,
                              void* d_out, int out_size) {
    const int*   kmer    = (const int*)  d_in[0];
    const float* emb     = (const float*)d_in[1];
    const float* psc     = (const float*)d_in[2];
    const float* norm_g  = (const float*)d_in[3];
    const float* Wh      = (const float*)d_in[4];
    const float* bh      = (const float*)d_in[5];
    const float* Wqk     = (const float*)d_in[6];
    const float* bqk     = (const float*)d_in[7];
    const float* gamma   = (const float*)d_in[8];
    const float* beta    = (const float*)d_in[9];
    const float* Wo      = (const float*)d_in[10];
    const float* bo      = (const float*)d_in[11];
    const float* fg      = (const float*)d_in[12];
    const float* Wl      = (const float*)d_in[13];
    const float* bl      = (const float*)d_in[14];
    const float* W1      = (const float*)d_in[15];
    const float* b1      = (const float*)d_in[16];
    const float* W2      = (const float*)d_in[17];
    const float* b2      = (const float*)d_in[18];
    float* out = (float*)d_out;

    cudaFuncSetAttribute(kA, cudaFuncAttributeMaxDynamicSharedMemorySize, KA_SMEM);
    cudaFuncSetAttribute(k_logits, cudaFuncAttributeMaxDynamicSharedMemorySize, LOGITS_SMEM);

    k_embed<<<(BN * DIM + 255) / 256, 256>>>(kmer, emb, psc);
    k_rot<<<(N * 16 + 255) / 256, 256>>>();

    for (int l = 0; l < DEPTH; l++) {
        const float* Whl = Wh + (long)l * 16 * 64;
        const float* bhl = bh + (long)l * 64;
        const float* Wql = Wqk + (long)l * 16 * 128;
        const float* bql = bqk + (long)l * 128;
        const float* gml = gamma + (long)l * 4 * 128;
        const float* btl = beta + (long)l * 4 * 128;
        kA<<<dim3(2, NG, B), 256, KA_SMEM>>>(norm_g + l, Whl, bhl, Wql, bql, gml, btl);
        kC<<<dim3(12, B), 256>>>(norm_g + l, Whl, bhl, Wql, bql, gml, btl,
                                 Wo + (long)l * 32 * DIM, bo + (long)l * DIM);
    }

    k_logits<<<BN / 16, 256, LOGITS_SMEM>>>(fg, Wl, bl);
    k_head<<<B, 256>>>(W1, b1, W2, b2, out);
    (void)in_sizes; (void)n_in; (void)out_size;
}

// round 17
// speedup vs baseline: 1.6493x; 1.5260x over previous
#include <cuda_runtime.h>
#include <math.h>

#define B 128
#define N 996
#define BN (B*N)
#define DIM 16
#define QKD 128
#define GSZ 256
#define NG 4
#define DEPTH 8
#define VOC 1024
#define ROTD 32

// ---------------- scratch ----------------
__device__ __align__(16) float g_x[BN*DIM];
__device__ __align__(16) float g_qo[BN*32];
__device__ __align__(16) float g_linkvp[B*8*128*32];
__device__ float g_rc[N*16];
__device__ float g_rs[N*16];
__device__ float g_hmax[BN];

#define ROT_LC 0.57564627324851142
#define POS_LC 1.1512925464970228

typedef unsigned long long ull;

__device__ __forceinline__ ull pk2(float a, float b) {
    ull r; asm("mov.b64 %0,{%1,%2};" : "=l"(r) : "f"(a), "f"(b)); return r;
}
__device__ __forceinline__ void fma2(ull& d, ull a, ull b) {
    asm("fma.rn.f32x2 %0,%1,%2,%0;" : "+l"(d) : "l"(a), "l"(b));
}
__device__ __forceinline__ float2 up2(ull v) {
    float2 f; asm("mov.b64 {%0,%1},%2;" : "=f"(f.x), "=f"(f.y) : "l"(v)); return f;
}
__device__ __forceinline__ float silu_f(float a) {
    return __fdividef(a, 1.0f + __expf(-a));
}
__device__ __forceinline__ unsigned f2tf(float f) {
    unsigned r; asm("cvt.rna.tf32.f32 %0,%1;" : "=r"(r) : "f"(f)); return r;
}
__device__ __forceinline__ void mma8(float* c, const unsigned* a, unsigned b0, unsigned b1) {
    asm volatile("mma.sync.aligned.m16n8k8.row.col.f32.tf32.tf32.f32 "
                 "{%0,%1,%2,%3},{%4,%5,%6,%7},{%8,%9},{%0,%1,%2,%3};"
                 : "+f"(c[0]), "+f"(c[1]), "+f"(c[2]), "+f"(c[3])
                 : "r"(a[0]), "r"(a[1]), "r"(a[2]), "r"(a[3]), "r"(b0), "r"(b1));
}

// proj 8 outputs [u0,u0+8)
__device__ __forceinline__ void proj8(const float* nmA, const float* nmB,
                                      const float* __restrict__ W, int ws,
                                      const float* __restrict__ bias, int u0, float* o) {
    #pragma unroll
    for (int j = 0; j < 8; j++) o[j] = bias[u0 + j];
    #pragma unroll
    for (int d = 0; d < 8; d++) { float a = nmA[d];
        #pragma unroll
        for (int j = 0; j < 8; j++) o[j] += a * W[d * ws + u0 + j]; }
    #pragma unroll
    for (int d = 0; d < 8; d++) { float a = nmB[d];
        #pragma unroll
        for (int j = 0; j < 8; j++) o[j] += a * W[(d + 8) * ws + u0 + j]; }
}
__device__ __forceinline__ void gbrot8(float* o, int u0, const float* __restrict__ gb, int pos) {
    #pragma unroll
    for (int jj = 0; jj < 8; jj++) o[jj] = silu_f(o[jj]);
    if (u0 < ROTD) {
        #pragma unroll
        for (int jj = 0; jj < 8; jj += 2) {
            int u = u0 + jj;
            float a = o[jj] * gb[u] + gb[128 + u];
            float b = o[jj+1] * gb[u+1] + gb[128 + u + 1];
            float c = g_rc[pos * 16 + (u >> 1)], s = g_rs[pos * 16 + (u >> 1)];
            o[jj] = a * c - b * s;
            o[jj+1] = b * c + a * s;
        }
    } else {
        #pragma unroll
        for (int jj = 0; jj < 8; jj++) { int u = u0 + jj; o[jj] = o[jj] * gb[u] + gb[128 + u]; }
    }
}

// ---------------- K0 / K0b ----------------
__global__ void k_embed(const int* __restrict__ kmer, const float* __restrict__ emb,
                        const float* __restrict__ ps) {
    int idx = blockIdx.x * blockDim.x + threadIdx.x;
    if (idx >= BN * DIM) return;
    int d = idx & 15;
    int tok = idx >> 4;
    int t = tok % N;
    int j = (d < 8) ? d : d - 8;
    float inv = (float)exp(-(double)j * POS_LC);
    float ang = (float)t * inv;
    float p = (d < 8) ? sinf(ang) : cosf(ang);
    g_x[idx] = emb[kmer[tok] * DIM + d] + p * ps[0];
}
__global__ void k_rot() {
    int idx = blockIdx.x * blockDim.x + threadIdx.x;
    if (idx >= N * 16) return;
    int t = idx >> 4, j = idx & 15;
    float inv = (float)exp(-(double)j * ROT_LC);
    float ang = (float)t * inv;
    g_rc[idx] = cosf(ang);
    g_rs[idx] = sinf(ang);
}

// ---------------- kA: fused norm+proj + tf32-mma quad attention + lin-KV partial ----------------
#define OF_SN  0
#define OF_QS  4372       // [128][132] fp32
#define OF_KTH 21268      // [128][72] tf32 hi
#define OF_KTL 30484
#define OF_VS  39700      // [64][40]
#define OF_WQK 42260
#define OF_WV  44308
#define OF_GBQ 44820
#define OF_GBK 45076
#define OF_BQK 45332
#define OF_BV  45460
#define OF_GB3 45492
#define OF_LK  45748      // [64][136]
#define KA_SMEM ((45748 + 8704 + 12) * 4)   // 217856 B

__global__ void __launch_bounds__(256, 1) kA(const float* __restrict__ ng,
        const float* __restrict__ Wh, const float* __restrict__ bh,
        const float* __restrict__ Wqk, const float* __restrict__ bqk,
        const float* __restrict__ gamma, const float* __restrict__ beta) {
    extern __shared__ float s[];
    float* SN = s + OF_SN;  float* QS = s + OF_QS;
    unsigned* KTH = (unsigned*)(s + OF_KTH);
    unsigned* KTL = (unsigned*)(s + OF_KTL);
    float* VS = s + OF_VS;  float* WQ = s + OF_WQK;
    float* WV = s + OF_WV;  float* GQ = s + OF_GBQ; float* GK = s + OF_GBK;
    float* BQ = s + OF_BQK; float* BV = s + OF_BV;  float* G3 = s + OF_GB3;
    float* LK = s + OF_LK;
    int tid = threadIdx.x;
    int lane = tid & 31, wid = tid >> 5;
    int r8 = lane >> 2, t4 = lane & 3;
    int qh = blockIdx.x, g = blockIdx.y, b = blockIdx.z;
    int gstart = g * GSZ;
    const int bN = b * N;

    for (int i = tid; i < 2048; i += 256) WQ[i] = Wqk[i];
    for (int i = tid; i < 512; i += 256) WV[i] = Wh[(i >> 5) * 64 + (i & 31)];
    if (tid < 128) {
        GQ[tid] = gamma[tid];       GQ[128 + tid] = beta[tid];
        GK[tid] = gamma[256 + tid]; GK[128 + tid] = beta[256 + tid];
        G3[tid] = gamma[384 + tid]; G3[128 + tid] = beta[384 + tid];
        BQ[tid] = bqk[tid];
    }
    if (tid < 32) BV[tid] = bh[tid];
    for (int i = tid; i < 257 * 4; i += 256) {
        int r = i >> 2, d4 = (i & 3) * 4;
        int p = gstart - 1 + r;
        float4 v = make_float4(0, 0, 0, 0);
        if (p >= 0 && p < N) v = *(const float4*)&g_x[(long)(bN + p) * 16 + d4];
        SN[r*17 + d4] = v.x; SN[r*17 + d4+1] = v.y; SN[r*17 + d4+2] = v.z; SN[r*17 + d4+3] = v.w;
    }
    __syncthreads();
    float gng = ng[0];
    for (int i = tid; i < 257; i += 256) {
        float ss = 0;
        #pragma unroll
        for (int d = 0; d < 16; d++) { float v = SN[i*17 + d]; ss += v * v; }
        float scl = gng / fmaxf(sqrtf(ss) * 0.25f, 1e-5f);
        #pragma unroll
        for (int d = 0; d < 16; d++) SN[i*17 + d] *= scl;
    }
    __syncthreads();

    {   // Q tile (128 q tokens x 128 dims) fp32
        int j = tid >> 1, h = tid & 1;
        int p = gstart + qh * 128 + j;
        int si = qh * 128 + j + 1;
        float nmA[8], nmB[8];
        bool first = (p == 0);
        #pragma unroll
        for (int d = 0; d < 8; d++) {
            nmA[d] = first ? 0.0f : SN[(si - 1) * 17 + d];
            nmB[d] = SN[si * 17 + 8 + d];
        }
        int rp = (p < N) ? p : 0;
        #pragma unroll
        for (int c = 0; c < 8; c++) {
            int u0 = h * 64 + c * 8;
            float o[8];
            proj8(nmA, nmB, WQ, 128, BQ, u0, o);
            gbrot8(o, u0, GQ, rp);
            #pragma unroll
            for (int jj = 0; jj < 8; jj += 2)
                *(float2*)&QS[j * 132 + u0 + jj] = make_float2(o[jj], o[jj+1]);
        }
    }

    float co[4][4];
    #pragma unroll
    for (int a = 0; a < 4; a++)
        #pragma unroll
        for (int i = 0; i < 4; i++) co[a][i] = 0.0f;
    ull lkacc[8];
    #pragma unroll
    for (int e = 0; e < 8; e++) lkacc[e] = 0ull;
    int dd = tid & 127, e0v = (tid >> 7) * 16;
    int mrow = wid * 16 + r8;

    for (int ck = 0; ck < 4; ck++) {
        bool mylin = (qh == (ck >> 1));
        __syncthreads();
        {   int t = tid & 63, q4 = tid >> 6;
            int kloc = ck * 64 + t;
            int p = gstart + kloc;
            int si = kloc + 1;
            float nmA[8], nmB[8];
            bool first = (p == 0);
            #pragma unroll
            for (int d = 0; d < 8; d++) {
                nmA[d] = first ? 0.0f : SN[(si - 1) * 17 + d];
                nmB[d] = SN[si * 17 + 8 + d];
            }
            int rp = (p < N) ? p : 0;
            #pragma unroll
            for (int cc = 0; cc < 4; cc++) {
                int u0 = q4 * 32 + cc * 8;
                float o[8];
                proj8(nmA, nmB, WQ, 128, BQ, u0, o);
                gbrot8(o, u0, GK, rp);
                #pragma unroll
                for (int jj = 0; jj < 8; jj++) {
                    unsigned h2 = f2tf(o[jj]);
                    KTH[(u0 + jj) * 72 + t] = h2;
                    KTL[(u0 + jj) * 72 + t] = f2tf(o[jj] - __uint_as_float(h2));
                }
            }
            {   int e0 = q4 * 8;
                float o[8];
                proj8(nmA, nmB, WV, 32, BV, e0, o);
                #pragma unroll
                for (int jj = 0; jj < 8; jj++) VS[t * 40 + e0 + jj] = silu_f(o[jj]);
            }
            if (mylin) {
                #pragma unroll
                for (int cc = 0; cc < 4; cc++) {
                    int u0 = q4 * 32 + cc * 8;
                    float o[8];
                    proj8(nmA, nmB, WQ, 128, BQ, u0, o);
                    gbrot8(o, u0, G3, rp);
                    #pragma unroll
                    for (int jj = 0; jj < 8; jj++)
                        LK[t * 136 + u0 + jj] = (p < N) ? o[jj] : 0.0f;
                }
            }
        }
        __syncthreads();

        float cs[8][4];
        #pragma unroll
        for (int nt = 0; nt < 8; nt++)
            #pragma unroll
            for (int i = 0; i < 4; i++) cs[nt][i] = 0.0f;
        #pragma unroll 2
        for (int kt = 0; kt < 16; kt++) {
            int kc0 = kt * 8 + t4;
            float q0 = QS[mrow * 132 + kc0];
            float q1 = QS[(mrow + 8) * 132 + kc0];
            float q2 = QS[mrow * 132 + kc0 + 4];
            float q3 = QS[(mrow + 8) * 132 + kc0 + 4];
            unsigned ah[4], al[4];
            ah[0] = f2tf(q0); al[0] = f2tf(q0 - __uint_as_float(ah[0]));
            ah[1] = f2tf(q1); al[1] = f2tf(q1 - __uint_as_float(ah[1]));
            ah[2] = f2tf(q2); al[2] = f2tf(q2 - __uint_as_float(ah[2]));
            ah[3] = f2tf(q3); al[3] = f2tf(q3 - __uint_as_float(ah[3]));
            #pragma unroll
            for (int nt = 0; nt < 8; nt++) {
                unsigned bh0 = KTH[kc0 * 72 + nt * 8 + r8];
                unsigned bh1 = KTH[(kc0 + 4) * 72 + nt * 8 + r8];
                unsigned bl0 = KTL[kc0 * 72 + nt * 8 + r8];
                unsigned bl1 = KTL[(kc0 + 4) * 72 + nt * 8 + r8];
                mma8(cs[nt], ah, bh0, bh1);
                mma8(cs[nt], ah, bl0, bl1);
                mma8(cs[nt], al, bh0, bh1);
            }
        }
        {   int kb = gstart + ck * 64;
            #pragma unroll
            for (int nt = 0; nt < 8; nt++) {
                int col0 = kb + nt * 8 + 2 * t4;
                float e00 = fmaxf(cs[nt][0] * (1.0f/256.0f), 0.0f); e00 *= e00;
                float e01 = fmaxf(cs[nt][1] * (1.0f/256.0f), 0.0f); e01 *= e01;
                float e10 = fmaxf(cs[nt][2] * (1.0f/256.0f), 0.0f); e10 *= e10;
                float e11 = fmaxf(cs[nt][3] * (1.0f/256.0f), 0.0f); e11 *= e11;
                if (col0     >= N) { e00 = 0.0f; e10 = 0.0f; }
                if (col0 + 1 >= N) { e01 = 0.0f; e11 = 0.0f; }
                unsigned u00 = f2tf(e00), u01 = f2tf(e01);
                unsigned u10 = f2tf(e10), u11 = f2tf(e11);
                int srcA = (lane & ~3) | (t4 >> 1);
                int srcB = srcA + 2;
                unsigned w00A = __shfl_sync(0xffffffffu, u00, srcA);
                unsigned w01A = __shfl_sync(0xffffffffu, u01, srcA);
                unsigned w10A = __shfl_sync(0xffffffffu, u10, srcA);
                unsigned w11A = __shfl_sync(0xffffffffu, u11, srcA);
                unsigned w00B = __shfl_sync(0xffffffffu, u00, srcB);
                unsigned w01B = __shfl_sync(0xffffffffu, u01, srcB);
                unsigned w10B = __shfl_sync(0xffffffffu, u10, srcB);
                unsigned w11B = __shfl_sync(0xffffffffu, u11, srcB);
                bool odd = (t4 & 1);
                unsigned aF[4];
                aF[0] = odd ? w01A : w00A;
                aF[1] = odd ? w11A : w10A;
                aF[2] = odd ? w01B : w00B;
                aF[3] = odd ? w11B : w10B;
                #pragma unroll
                for (int av = 0; av < 4; av++) {
                    float v0 = VS[(nt * 8 + t4) * 40 + av * 8 + r8];
                    float v1 = VS[(nt * 8 + t4 + 4) * 40 + av * 8 + r8];
                    unsigned bh0 = f2tf(v0), bh1 = f2tf(v1);
                    unsigned bl0 = f2tf(v0 - __uint_as_float(bh0));
                    unsigned bl1 = f2tf(v1 - __uint_as_float(bh1));
                    mma8(co[av], aF, bh0, bh1);
                    mma8(co[av], aF, bl0, bl1);
                }
            }
        }
        if (mylin) {
            #pragma unroll 4
            for (int j = 0; j < 64; j++) {
                float lv = LK[j * 136 + dd];
                ull ld = pk2(lv, lv);
                const ull* vp = (const ull*)&VS[j * 40 + e0v];
                #pragma unroll
                for (int e = 0; e < 8; e++) fma2(lkacc[e], ld, vp[e]);
            }
        }
    }
    {   int qp0 = gstart + qh * 128 + mrow;
        #pragma unroll
        for (int av = 0; av < 4; av++) {
            if (qp0 < N)
                *(float2*)&g_qo[(long)(bN + qp0) * 32 + av * 8 + 2 * t4] =
                    make_float2(co[av][0], co[av][1]);
            if (qp0 + 8 < N)
                *(float2*)&g_qo[(long)(bN + qp0 + 8) * 32 + av * 8 + 2 * t4] =
                    make_float2(co[av][2], co[av][3]);
        }
    }
    {   float* dst = &g_linkvp[((long)(b * 8 + g * 2 + qh) * 128 + dd) * 32 + e0v];
        #pragma unroll
        for (int e = 0; e < 8; e++) { float2 f = up2(lkacc[e]); *(float2*)&dst[e * 2] = f; }
    }
}

// ---------------- kC: KV-reduce + lin_out (tiled) + gate + Wo + residual ----------------
__global__ void __launch_bounds__(256, 2) kC(const float* __restrict__ ng,
        const float* __restrict__ Wh, const float* __restrict__ bh,
        const float* __restrict__ Wqk, const float* __restrict__ bqk,
        const float* __restrict__ gamma, const float* __restrict__ beta,
        const float* __restrict__ Wo, const float* __restrict__ bo) {
    __shared__ __align__(16) float SN[84 * 17];
    __shared__ __align__(16) float SKV[4096];
    __shared__ __align__(16) float WQ[2048];
    __shared__ __align__(16) float WG[512];
    __shared__ __align__(16) float GB[256];
    __shared__ __align__(16) float BQ2[128];
    __shared__ __align__(16) float BG[32];
    __shared__ __align__(16) float SWO[512];
    __shared__ __align__(16) float SBO[16];
    __shared__ __align__(16) float SLQ[32 * 132];
    __shared__ __align__(16) float SG[32 * 33];
    __shared__ __align__(16) float OV[32 * 34];
    int tid = threadIdx.x;
    int ch = blockIdx.x, b = blockIdx.y;
    const int bN = b * N;
    int t0 = ch * 83;

    for (int i = tid; i < 2048; i += 256) WQ[i] = Wqk[i];
    for (int i = tid; i < 512; i += 256) {
        WG[i] = Wh[(i >> 5) * 64 + 32 + (i & 31)];
        SWO[i] = Wo[i];
    }
    if (tid < 128) {
        GB[tid] = gamma[128 + tid]; GB[128 + tid] = beta[128 + tid];
        BQ2[tid] = bqk[tid];
    }
    if (tid < 32) BG[tid] = bh[32 + tid];
    if (tid < 16) SBO[tid] = bo[tid];
    const float inv_n = 1.0f / (float)N;
    for (int i = tid; i < 1024; i += 256) {
        float4 ssum = make_float4(0, 0, 0, 0);
        #pragma unroll
        for (int k2 = 0; k2 < 8; k2++) {
            float4 p = ((const float4*)&g_linkvp[(long)(b * 8 + k2) * 4096])[i];
            ssum.x += p.x; ssum.y += p.y; ssum.z += p.z; ssum.w += p.w;
        }
        ((float4*)SKV)[i] = make_float4(ssum.x * inv_n, ssum.y * inv_n, ssum.z * inv_n, ssum.w * inv_n);
    }
    for (int i = tid; i < 84 * 4; i += 256) {
        int r = i >> 2, d4 = (i & 3) * 4;
        int p = t0 - 1 + r;
        float4 v = make_float4(0, 0, 0, 0);
        if (p >= 0 && p < N) v = *(const float4*)&g_x[(long)(bN + p) * 16 + d4];
        SN[r*17 + d4] = v.x; SN[r*17 + d4+1] = v.y; SN[r*17 + d4+2] = v.z; SN[r*17 + d4+3] = v.w;
    }
    __syncthreads();
    float gng = ng[0];
    for (int i = tid; i < 84; i += 256) {
        float ss = 0;
        #pragma unroll
        for (int d = 0; d < 16; d++) { float v = SN[i*17 + d]; ss += v * v; }
        float scl = gng / fmaxf(sqrtf(ss) * 0.25f, 1e-5f);
        #pragma unroll
        for (int d = 0; d < 16; d++) SN[i*17 + d] *= scl;
    }

    int w = tid >> 5, lane = tid & 31;
    for (int tb = 0; tb < 96; tb += 32) {
        __syncthreads();
        #pragma unroll
        for (int i = 0; i < 4; i++) {
            int ltl = w * 4 + i;
            int lt = tb + ltl;
            int ltc = min(lt, 82);
            int tok = t0 + ltc;
            int si = ltc + 1;
            bool first = (tok == 0);
            float nmA[8], nmB[8];
            #pragma unroll
            for (int d = 0; d < 8; d++) {
                nmA[d] = first ? 0.0f : SN[(si - 1) * 17 + d];
                nmB[d] = SN[si * 17 + 8 + d];
            }
            #pragma unroll
            for (int j = 0; j < 4; j++) {
                int u = lane + 32 * j;
                float o = BQ2[u];
                #pragma unroll
                for (int d = 0; d < 8; d++) o += nmA[d] * WQ[d * 128 + u];
                #pragma unroll
                for (int d = 0; d < 8; d++) o += nmB[d] * WQ[(d + 8) * 128 + u];
                o = silu_f(o);
                o = o * GB[u] + GB[128 + u];
                if (j == 0) {
                    float c = g_rc[tok * 16 + (lane >> 1)], sn2 = g_rs[tok * 16 + (lane >> 1)];
                    float part = __shfl_xor_sync(0xffffffffu, o, 1);
                    o = (lane & 1) ? (o * c + part * sn2) : (o * c - part * sn2);
                }
                SLQ[ltl * 132 + u] = o;
            }
            {   float o = BG[lane];
                #pragma unroll
                for (int d = 0; d < 8; d++) o += nmA[d] * WG[d * 32 + lane];
                #pragma unroll
                for (int d = 0; d < 8; d++) o += nmB[d] * WG[(d + 8) * 32 + lane];
                SG[ltl * 33 + lane] = silu_f(o);
            }
        }
        __syncthreads();
        {
            int tt = tid >> 3;
            int e4 = (tid & 7) * 4;
            ull a0 = 0ull, a1 = 0ull, b0 = 0ull, b1 = 0ull;
            #pragma unroll 8
            for (int d = 0; d < 128; d += 2) {
                float q0 = SLQ[tt * 132 + d];
                float q1 = SLQ[tt * 132 + d + 1];
                ulonglong2 kv0 = *(const ulonglong2*)&SKV[d * 32 + e4];
                ulonglong2 kv1 = *(const ulonglong2*)&SKV[(d + 1) * 32 + e4];
                ull qd0 = pk2(q0, q0), qd1 = pk2(q1, q1);
                fma2(a0, qd0, kv0.x); fma2(a1, qd0, kv0.y);
                fma2(b0, qd1, kv1.x); fma2(b1, qd1, kv1.y);
            }
            float2 fa0 = up2(a0), fa1 = up2(a1), fb0 = up2(b0), fb1 = up2(b1);
            int lt = tb + tt;
            int ltc = min(lt, 82);
            int tok = t0 + ltc;
            float4 qo = *(const float4*)&g_qo[(long)(bN + tok) * 32 + e4];
            float g0 = SG[tt * 33 + e4],     g1 = SG[tt * 33 + e4 + 1];
            float g2 = SG[tt * 33 + e4 + 2], g3 = SG[tt * 33 + e4 + 3];
            OV[tt * 34 + e4]     = (qo.x + fa0.x + fb0.x) * g0;
            OV[tt * 34 + e4 + 1] = (qo.y + fa0.y + fb0.y) * g1;
            OV[tt * 34 + e4 + 2] = (qo.z + fa1.x + fb1.x) * g2;
            OV[tt * 34 + e4 + 3] = (qo.w + fa1.y + fb1.y) * g3;
        }
        __syncthreads();
        {
            int dcol = tid & 15;
            int tt2 = tid >> 4;
            #pragma unroll
            for (int h = 0; h < 2; h++) {
                int ttw = tt2 + 16 * h;
                int lt = tb + ttw;
                if (lt < 83) {
                    float y = SBO[dcol];
                    #pragma unroll
                    for (int e = 0; e < 32; e++) y += OV[ttw * 34 + e] * SWO[e * 16 + dcol];
                    g_x[(long)(bN + t0 + lt) * 16 + dcol] += y;
                }
            }
        }
    }
}

// ---------------- k_logits / k_head ----------------
#define LOGITS_SMEM ((16*1024 + 1024 + 16*16) * 4)
__global__ void k_logits(const float* __restrict__ fg, const float* __restrict__ Wl,
                         const float* __restrict__ blv) {
    extern __shared__ float sm[];
    float* sW = sm;
    float* sb = sW + 16 * 1024;
    float* xn = sb + 1024;
    __shared__ float wred[8];
    __shared__ float xs[16];
    int tid = threadIdx.x;
    int base = blockIdx.x * 16;
    for (int i = tid; i < (16 * 1024) / 4; i += 256)
        ((float4*)sW)[i] = ((const float4*)Wl)[i];
    for (int i = tid; i < 1024; i += 256) sb[i] = blv[i];
    {   int tt = tid >> 4, d = tid & 15;
        xn[tt * 16 + d] = g_x[(long)(base + tt) * DIM + d];
    }
    __syncthreads();
    if (tid < 16) {
        float ss = 0;
        #pragma unroll
        for (int d = 0; d < 16; d++) { float v = xn[tid * 16 + d]; ss += v * v; }
        xs[tid] = fg[0] / fmaxf(sqrtf(ss) * 0.25f, 1e-5f);
    }
    __syncthreads();
    {   int tt = tid >> 4, d = tid & 15;
        xn[tt * 16 + d] *= xs[tt];
    }
    __syncthreads();
    int warp = tid >> 5, lane = tid & 31;
    int v0 = tid * 4;
    for (int tt = 0; tt < 16; tt++) {
        float s0 = sb[v0], s1 = sb[v0+1], s2 = sb[v0+2], s3 = sb[v0+3];
        #pragma unroll
        for (int d = 0; d < 16; d++) {
            float xv = xn[tt * 16 + d];
            float4 wv = *(const float4*)&sW[d * 1024 + v0];
            s0 += xv * wv.x; s1 += xv * wv.y; s2 += xv * wv.z; s3 += xv * wv.w;
        }
        float m = fmaxf(fmaxf(s0, s1), fmaxf(s2, s3));
        #pragma unroll
        for (int off = 16; off > 0; off >>= 1)
            m = fmaxf(m, __shfl_xor_sync(0xffffffff, m, off));
        if (lane == 0) wred[warp] = m;
        __syncthreads();
        if (tid == 0) {
            float mm = wred[0];
            #pragma unroll
            for (int j = 1; j < 8; j++) mm = fmaxf(mm, wred[j]);
            g_hmax[base + tt] = mm;
        }
        __syncthreads();
    }
}
__global__ void k_head(const float* __restrict__ W1, const float* __restrict__ b1,
                       const float* __restrict__ W2, const float* __restrict__ b2,
                       float* __restrict__ out) {
    __shared__ float red[8][32];
    __shared__ float rr[32];
    int tid = threadIdx.x;
    int b = blockIdx.x;
    int col = tid & 31, seg = tid >> 5;
    float acc = 0.0f;
    int t0 = seg * 125;
    int t1 = min(t0 + 125, N);
    for (int t = t0; t < t1; t++)
        acc += g_hmax[(long)b * N + t] * W1[t * 32 + col];
    red[seg][col] = acc;
    __syncthreads();
    if (tid < 32) {
        float ss = b1[tid];
        #pragma unroll
        for (int k = 0; k < 8; k++) ss += red[k][tid];
        rr[tid] = fmaxf(ss, 0.0f);
    }
    __syncthreads();
    if (tid == 0) {
        float o = b2[0];
        #pragma unroll
        for (int j = 0; j < 32; j++) o += rr[j] * W2[j];
        out[b] = o;
    }
}

// ---------------- launch ----------------
extern "C" void kernel_launch(void* const* d_in, const int* in_sizes, int n_in,
                              void* d_out, int out_size) {
    const int*   kmer    = (const int*)  d_in[0];
    const float* emb     = (const float*)d_in[1];
    const float* psc     = (const float*)d_in[2];
    const float* norm_g  = (const float*)d_in[3];
    const float* Wh      = (const float*)d_in[4];
    const float* bh      = (const float*)d_in[5];
    const float* Wqk     = (const float*)d_in[6];
    const float* bqk     = (const float*)d_in[7];
    const float* gamma   = (const float*)d_in[8];
    const float* beta    = (const float*)d_in[9];
    const float* Wo      = (const float*)d_in[10];
    const float* bo      = (const float*)d_in[11];
    const float* fg      = (const float*)d_in[12];
    const float* Wl      = (const float*)d_in[13];
    const float* bl      = (const float*)d_in[14];
    const float* W1      = (const float*)d_in[15];
    const float* b1      = (const float*)d_in[16];
    const float* W2      = (const float*)d_in[17];
    const float* b2      = (const float*)d_in[18];
    float* out = (float*)d_out;

    cudaFuncSetAttribute(kA, cudaFuncAttributeMaxDynamicSharedMemorySize, KA_SMEM);
    cudaFuncSetAttribute(k_logits, cudaFuncAttributeMaxDynamicSharedMemorySize, LOGITS_SMEM);

    k_embed<<<(BN * DIM + 255) / 256, 256>>>(kmer, emb, psc);
    k_rot<<<(N * 16 + 255) / 256, 256>>>();

    for (int l = 0; l < DEPTH; l++) {
        const float* Whl = Wh + (long)l * 16 * 64;
        const float* bhl = bh + (long)l * 64;
        const float* Wql = Wqk + (long)l * 16 * 128;
        const float* bql = bqk + (long)l * 128;
        const float* gml = gamma + (long)l * 4 * 128;
        const float* btl = beta + (long)l * 4 * 128;
        kA<<<dim3(2, NG, B), 256, KA_SMEM>>>(norm_g + l, Whl, bhl, Wql, bql, gml, btl);
        kC<<<dim3(12, B), 256>>>(norm_g + l, Whl, bhl, Wql, bql, gml, btl,
                                 Wo + (long)l * 32 * DIM, bo + (long)l * DIM);
    }

    k_logits<<<BN / 16, 256, LOGITS_SMEM>>>(fg, Wl, bl);
    k_head<<<B, 256>>>(W1, b1, W2, b2, out);
    (void)in_sizes; (void)n_in; (void)out_size;
}